// round 1
// baseline (speedup 1.0000x reference)
#include <cuda_runtime.h>
#include <math.h>

#define TT 512      // sequence length
#define DD 512      // model dim
#define LOG2E 1.4426950408889634f

// Scratch (allocation-free rule: device globals)
__device__ float g_qkv[3 * DD * TT];   // [w][o][t]  w=0:q 1:k 2:v
__device__ float g_ao[DD * TT];        // attention output [o][t]

__device__ __forceinline__ float fast_ex2(float x) {
    float r;
    asm("ex2.approx.ftz.f32 %0, %1;" : "=f"(r) : "f"(x));
    return r;
}

// ---------------------------------------------------------------------------
// GEMM 1: fused QKV projection.
// C[n][m] = sum_k W[n%512][k] * X[m][k],  n in [0,1536), m in [0,512)
// Tiles: 32 (m) x 64 (n), K-tile 16. 256 threads, each 2x4 outputs.
// ---------------------------------------------------------------------------
__global__ void qkv_gemm_kernel(const float* __restrict__ x,
                                const float* __restrict__ Wq,
                                const float* __restrict__ Wk,
                                const float* __restrict__ Wv) {
    __shared__ float Ws[16][68];  // [k][n]
    __shared__ float Xs[16][36];  // [k][m]

    const int m0 = blockIdx.x * 32;
    const int n0 = blockIdx.y * 64;
    const float* W = (n0 < 512) ? Wq : (n0 < 1024 ? Wk : Wv);
    const int nbase = n0 & 511;

    const int tx = threadIdx.x;            // 0..15 -> m
    const int ty = threadIdx.y;            // 0..15 -> n
    const int tid = ty * 16 + tx;

    // W tile load mapping: 64 rows x 16 k, one float4 per thread
    const int wlr = tid >> 2;              // 0..63 (n row)
    const int wlc = (tid & 3) * 4;         // k col
    // X tile load mapping: 32 rows x 16 k, one float2 per thread
    const int xlr = tid >> 3;              // 0..31 (m row)
    const int xlc = (tid & 7) * 2;         // k col

    float acc[2][4];
#pragma unroll
    for (int i = 0; i < 2; i++)
#pragma unroll
        for (int j = 0; j < 4; j++) acc[i][j] = 0.f;

    for (int k0 = 0; k0 < DD; k0 += 16) {
        float4 w4 = *(const float4*)&W[(nbase + wlr) * DD + k0 + wlc];
        float2 x2 = *(const float2*)&x[(m0 + xlr) * DD + k0 + xlc];
        Ws[wlc + 0][wlr] = w4.x;
        Ws[wlc + 1][wlr] = w4.y;
        Ws[wlc + 2][wlr] = w4.z;
        Ws[wlc + 3][wlr] = w4.w;
        Xs[xlc + 0][xlr] = x2.x;
        Xs[xlc + 1][xlr] = x2.y;
        __syncthreads();
#pragma unroll
        for (int kk = 0; kk < 16; kk++) {
            float a0 = Xs[kk][tx * 2 + 0];
            float a1 = Xs[kk][tx * 2 + 1];
            float4 b = *(const float4*)&Ws[kk][ty * 4];
            acc[0][0] += a0 * b.x; acc[0][1] += a0 * b.y;
            acc[0][2] += a0 * b.z; acc[0][3] += a0 * b.w;
            acc[1][0] += a1 * b.x; acc[1][1] += a1 * b.y;
            acc[1][2] += a1 * b.z; acc[1][3] += a1 * b.w;
        }
        __syncthreads();
    }

#pragma unroll
    for (int j = 0; j < 4; j++)
#pragma unroll
        for (int i = 0; i < 2; i++)
            g_qkv[(n0 + ty * 4 + j) * TT + m0 + tx * 2 + i] = acc[i][j];
}

// ---------------------------------------------------------------------------
// RoPE (rotation across the HEADS axis, per reference's rotate_half on axis=1)
// One thread per (c, t); handles all 8 heads of q and k in place.
// ---------------------------------------------------------------------------
__global__ void rope_kernel() {
    const int gid = blockIdx.x * blockDim.x + threadIdx.x;  // 0..32767
    const int t = gid & 511;
    const int c = gid >> 9;      // 0..63
    const int fi = c & 31;

    // Match jnp fp32 table: invf = fp32(10000^(-2*fi/64)); ang = fp32(t)*invf
    float invf = (float)pow(10000.0, -(double)(2 * fi) / 64.0);
    float ang = (float)t * invf;
    float cv = (float)cos((double)ang);
    float sv = (float)sin((double)ang);

#pragma unroll
    for (int w = 0; w < 2; w++) {            // q then k
        float* base = g_qkv + w * DD * TT;
        float vals[8];
#pragma unroll
        for (int h = 0; h < 8; h++) vals[h] = base[(h * 64 + c) * TT + t];
#pragma unroll
        for (int h = 0; h < 8; h++) {
            float rot = (h < 4) ? -vals[h + 4] : vals[h - 4];
            base[(h * 64 + c) * TT + t] = vals[h] * cv + rot * sv;
        }
    }
}

// ---------------------------------------------------------------------------
// Per-channel causal softmax attention.
// Channel c: out[i] = sum_{j<=i} softmax_j(q[i]*k[j]*scale) * v[j]
// Scores are O(few) in magnitude -> no max subtraction needed in fp32.
// One block per channel; thread tid handles queries i=tid and i=511-tid
// (balanced: (tid+1) + (512-tid) = 513 iterations each thread).
// ---------------------------------------------------------------------------
__global__ void attn_kernel() {
    const int c = blockIdx.x;  // 0..511
    const float* q = g_qkv + 0 * DD * TT + c * TT;
    const float* k = g_qkv + 1 * DD * TT + c * TT;
    const float* v = g_qkv + 2 * DD * TT + c * TT;

    __shared__ float ks[512];
    __shared__ float vs[512];
    const int tid = threadIdx.x;  // 0..255
    ks[tid]       = k[tid];
    ks[tid + 256] = k[tid + 256];
    vs[tid]       = v[tid];
    vs[tid + 256] = v[tid + 256];
    __syncthreads();

#pragma unroll
    for (int rep = 0; rep < 2; rep++) {
        const int i = rep ? (511 - tid) : tid;
        const float qs = q[i] * (0.125f * LOG2E);  // scale=1/sqrt(64), log2e folded
        float l = 0.f, acc = 0.f;
#pragma unroll 4
        for (int j = 0; j <= i; j++) {
            float p = fast_ex2(qs * ks[j]);
            l += p;
            acc += p * vs[j];
        }
        g_ao[c * TT + i] = acc / l;
    }
}

// ---------------------------------------------------------------------------
// GEMM 2: output projection.
// y[m][n] = sum_k Wo[n][k] * A[k][m]   (A = g_ao, [o][t] layout -> k=o, m=t)
// Tiles: 32 (m) x 64 (n), K-tile 16.
// ---------------------------------------------------------------------------
__global__ void out_gemm_kernel(const float* __restrict__ Wo,
                                float* __restrict__ y) {
    __shared__ float Ws[16][68];  // [k][n]
    __shared__ float As[16][36];  // [k][m]

    const int m0 = blockIdx.x * 32;  // t
    const int n0 = blockIdx.y * 64;  // o

    const int tx = threadIdx.x;
    const int ty = threadIdx.y;
    const int tid = ty * 16 + tx;

    const int wlr = tid >> 2;
    const int wlc = (tid & 3) * 4;
    const int ar = tid >> 4;          // 0..15 (k row)
    const int ac = (tid & 15) * 2;    // m col

    float acc[2][4];
#pragma unroll
    for (int i = 0; i < 2; i++)
#pragma unroll
        for (int j = 0; j < 4; j++) acc[i][j] = 0.f;

    for (int k0 = 0; k0 < DD; k0 += 16) {
        float4 w4 = *(const float4*)&Wo[(n0 + wlr) * DD + k0 + wlc];
        float2 a2 = *(const float2*)&g_ao[(k0 + ar) * TT + m0 + ac];
        Ws[wlc + 0][wlr] = w4.x;
        Ws[wlc + 1][wlr] = w4.y;
        Ws[wlc + 2][wlr] = w4.z;
        Ws[wlc + 3][wlr] = w4.w;
        As[ar][ac + 0] = a2.x;
        As[ar][ac + 1] = a2.y;
        __syncthreads();
#pragma unroll
        for (int kk = 0; kk < 16; kk++) {
            float a0 = As[kk][tx * 2 + 0];
            float a1 = As[kk][tx * 2 + 1];
            float4 b = *(const float4*)&Ws[kk][ty * 4];
            acc[0][0] += a0 * b.x; acc[0][1] += a0 * b.y;
            acc[0][2] += a0 * b.z; acc[0][3] += a0 * b.w;
            acc[1][0] += a1 * b.x; acc[1][1] += a1 * b.y;
            acc[1][2] += a1 * b.z; acc[1][3] += a1 * b.w;
        }
        __syncthreads();
    }

#pragma unroll
    for (int i = 0; i < 2; i++)
#pragma unroll
        for (int j = 0; j < 4; j++)
            y[(m0 + tx * 2 + i) * DD + n0 + ty * 4 + j] = acc[i][j];
}

// ---------------------------------------------------------------------------
extern "C" void kernel_launch(void* const* d_in, const int* in_sizes, int n_in,
                              void* d_out, int out_size) {
    const float* x  = (const float*)d_in[0];
    const float* Wq = (const float*)d_in[1];
    const float* Wk = (const float*)d_in[2];
    const float* Wv = (const float*)d_in[3];
    const float* Wo = (const float*)d_in[4];
    float* y = (float*)d_out;

    dim3 blk(16, 16);
    qkv_gemm_kernel<<<dim3(512 / 32, 1536 / 64), blk>>>(x, Wq, Wk, Wv);
    rope_kernel<<<128, 256>>>();
    attn_kernel<<<512, 256>>>();
    out_gemm_kernel<<<dim3(512 / 32, 512 / 64), blk>>>(Wo, y);
}